// round 17
// baseline (speedup 1.0000x reference)
#include <cuda_runtime.h>
#include <cuda_fp16.h>
#include <cstdint>

// Problem dims (fixed)
#define BB 4
#define TT 4096
#define HH 2048
#define LL 4
#define MROWS 16384
#define N3H 6144
#define KDIM 2048

// ---------------- scratch (__device__ globals; referenced ONLY in device code)
__device__ float  g_BCx[(size_t)MROWS * N3H];     // 384 MB fp32
__device__ __half g_xh[(size_t)MROWS * HH];
__device__ __half g_yh[(size_t)MROWS * HH];
__device__ __half g_Wi16[(size_t)HH * N3H];       // W_in  [2048][6144] fp16 (K-major)
__device__ __half g_Wo16[(size_t)HH * HH];        // W_out [2048][2048] fp16 (K-major)

// ---------------- PTX helpers (plain sm_103-safe) ----------------------------
__device__ __forceinline__ uint32_t smem_u32(const void* p) {
    uint32_t a;
    asm("{ .reg .u64 t; cvta.to.shared.u64 t, %1; cvt.u32.u64 %0, t; }" : "=r"(a) : "l"(p));
    return a;
}
#define SWZ64(off)  ((off) ^ (((off) >> 3) & 0x30))   // 64B rows (A, BK=32)
#define SWZ128(off) ((off) ^ (((off) >> 3) & 0x70))   // 128B rows (A, BK=64)
#define SWZ256(off) ((off) ^ (((off) >> 4) & 0x70))   // 256B rows (B)

#define CP_ASYNC16(dst, src) \
    asm volatile("cp.async.cg.shared.global [%0], [%1], 16;" :: "r"(dst), "l"(src))
#define CP_ASYNC_COMMIT() asm volatile("cp.async.commit_group;")
#define CP_ASYNC_WAIT(n)  asm volatile("cp.async.wait_group %0;" :: "n"(n))

#define LDSM_X4(r0, r1, r2, r3, addr) \
    asm volatile("ldmatrix.sync.aligned.m8n8.x4.shared.b16 {%0,%1,%2,%3}, [%4];" \
        : "=r"(r0), "=r"(r1), "=r"(r2), "=r"(r3) : "r"(addr))
#define LDSM_X4_T(r0, r1, r2, r3, addr) \
    asm volatile("ldmatrix.sync.aligned.m8n8.x4.trans.shared.b16 {%0,%1,%2,%3}, [%4];" \
        : "=r"(r0), "=r"(r1), "=r"(r2), "=r"(r3) : "r"(addr))

// NOT volatile: pure register computation; ptxas may schedule freely.
#define MMA16816(d, a, b0, b1) \
    asm("mma.sync.aligned.m16n8k16.row.col.f32.f16.f16.f32 " \
        "{%0,%1,%2,%3}, {%4,%5,%6,%7}, {%8,%9}, {%0,%1,%2,%3};" \
        : "+f"((d)[0]), "+f"((d)[1]), "+f"((d)[2]), "+f"((d)[3]) \
        : "r"((a)[0]), "r"((a)[1]), "r"((a)[2]), "r"((a)[3]), "r"(b0), "r"(b1))

// ---------------- prep kernels ----------------------------------------------
__global__ __launch_bounds__(256)
void convert_x_kernel(const float* __restrict__ x)
{
    size_t i = ((size_t)blockIdx.x * 256 + threadIdx.x) * 4;
    float4 v = *(const float4*)(x + i);
    __half h[4] = {__float2half(v.x), __float2half(v.y),
                   __float2half(v.z), __float2half(v.w)};
    *(uint2*)(g_xh + i) = *(uint2*)h;
}

__global__ __launch_bounds__(256)
void convert_w_kernel(const float* __restrict__ in, int wsel)
{
    __half* __restrict__ o = wsel ? g_Wo16 : g_Wi16;
    size_t i = ((size_t)blockIdx.x * 256 + threadIdx.x) * 4;
    float4 v = *(const float4*)(in + i);
    __half h[4] = {__float2half(v.x), __float2half(v.y),
                   __float2half(v.z), __float2half(v.w)};
    *(uint2*)(o + i) = *(uint2*)h;
}

// ============================================================================
// Variant A (preferred): BK=64, dynamic smem 96 KB (3 stages x 32 KB)
// A tile 128r x 128B (SW128); B tile 64r x 256B (SWZ256, ldmatrix.trans)
// ============================================================================
#define DYN_NITER 32
#define DYN_TILEB 16384
#define DYN_STG_B (2 * DYN_TILEB)     // 32 KB
#define DYN_SMEM  (3 * DYN_STG_B)     // 96 KB

__global__ __launch_bounds__(256, 2)
void gemm_mma_dyn(int gsel, float* __restrict__ Cout)
{
    const __half* __restrict__ A = gsel ? g_yh : g_xh;
    const __half* __restrict__ B = gsel ? g_Wo16 : g_Wi16;
    float* __restrict__ C  = gsel ? Cout : g_BCx;
    const int Cw = gsel ? HH : N3H;     // also B row stride

    extern __shared__ __align__(1024) char smem[];
    const int tid = threadIdx.x;
    const int wid = tid >> 5;
    const int lid = tid & 31;
    const int wm = wid & 3;
    const int wn = wid >> 2;
    const int bm = blockIdx.y * 128;
    const int bn = blockIdx.x * 128;

    float acc[2][8][4];
    #pragma unroll
    for (int t = 0; t < 2; ++t)
        #pragma unroll
        for (int j = 0; j < 8; ++j)
            #pragma unroll
            for (int e = 0; e < 4; ++e) acc[t][j][e] = 0.f;

    const int a_row = (lid & 15);
    const int a_kb  = (lid & 16) ? 16 : 0;
    const int bsel  = lid >> 3;
    const int b_kin = (bsel & 1) * 8 + (lid & 7);
    const int b_nin = (bsel >> 1) * 8;

    // loader: 2048 chunks of 16B per stage -> 8 per thread
    auto load_stage = [&](char* sbase, int k0) {
        #pragma unroll
        for (int j = 0; j < 8; ++j) {
            int c = tid + j * 256;              // 0..2047
            if (c < 1024) {                     // A: 128 rows x 8 chunks
                int r = c >> 3, ch = c & 7;
                const __half* src = A + (size_t)(bm + r) * KDIM + k0 + ch * 8;
                uint32_t dst = smem_u32(sbase);
                CP_ASYNC16(dst + SWZ128(r * 128 + ch * 16), src);
            } else {                            // B: 64 k-rows x 16 chunks
                int cc = c - 1024;
                int r = cc >> 4, ch = cc & 15;
                const __half* src = B + (size_t)(k0 + r) * Cw + bn + ch * 8;
                uint32_t dst = smem_u32(sbase + DYN_TILEB);
                CP_ASYNC16(dst + SWZ256(r * 256 + ch * 16), src);
            }
        }
        CP_ASYNC_COMMIT();
    };

    load_stage(smem,             0);
    load_stage(smem + DYN_STG_B, 64);

    int cur = 0;
    for (int i = 0; i < DYN_NITER; ++i) {
        if (i + 1 < DYN_NITER) { CP_ASYNC_WAIT(1); } else { CP_ASYNC_WAIT(0); }
        __syncthreads();

        char* sbase = smem + cur * DYN_STG_B;
        const uint32_t tA = smem_u32(sbase);
        const uint32_t tB = tA + DYN_TILEB;

        #pragma unroll
        for (int kk = 0; kk < 4; ++kk) {
            uint32_t av[2][4], bv[4][4];
            #pragma unroll
            for (int t = 0; t < 2; ++t) {
                int row = wm * 32 + t * 16 + a_row;
                LDSM_X4(av[t][0], av[t][1], av[t][2], av[t][3],
                        tA + SWZ128(row * 128 + kk * 32 + a_kb));
            }
            #pragma unroll
            for (int g = 0; g < 4; ++g) {
                int krow = kk * 16 + b_kin;
                int ncol = wn * 64 + g * 16 + b_nin;
                LDSM_X4_T(bv[g][0], bv[g][1], bv[g][2], bv[g][3],
                          tB + SWZ256(krow * 256 + ncol * 2));
            }
            #pragma unroll
            for (int t = 0; t < 2; ++t)
                #pragma unroll
                for (int g = 0; g < 4; ++g) {
                    MMA16816(acc[t][2 * g],     av[t], bv[g][0], bv[g][1]);
                    MMA16816(acc[t][2 * g + 1], av[t], bv[g][2], bv[g][3]);
                }
        }

        if (i + 2 < DYN_NITER) {
            int nxt = cur + 2; if (nxt >= 3) nxt -= 3;
            load_stage(smem + nxt * DYN_STG_B, (i + 2) * 64);
        }
        if (++cur == 3) cur = 0;
    }

    const int r0 = bm + wm * 32 + (lid >> 2);
    const int cb = bn + wn * 64 + (lid & 3) * 2;
    #pragma unroll
    for (int t = 0; t < 2; ++t)
        #pragma unroll
        for (int j = 0; j < 8; ++j) {
            float2 v0 = make_float2(acc[t][j][0], acc[t][j][1]);
            float2 v1 = make_float2(acc[t][j][2], acc[t][j][3]);
            *(float2*)(C + (size_t)(r0 + t * 16)     * Cw + cb + j * 8) = v0;
            *(float2*)(C + (size_t)(r0 + t * 16 + 8) * Cw + cb + j * 8) = v1;
        }
}

// ============================================================================
// Variant B (fallback): BK=32, static 48 KB (the proven R16 kernel)
// ============================================================================
#define ST_NITER 64
#define ST_TILEB 8192
#define ST_STG_B (2 * ST_TILEB)

__global__ __launch_bounds__(256, 2)
void gemm_mma_static(int gsel, float* __restrict__ Cout)
{
    const __half* __restrict__ A = gsel ? g_yh : g_xh;
    const __half* __restrict__ B = gsel ? g_Wo16 : g_Wi16;
    float* __restrict__ C  = gsel ? Cout : g_BCx;
    const int Cw = gsel ? HH : N3H;

    __shared__ __align__(1024) char smem[3 * ST_STG_B];
    const int tid = threadIdx.x;
    const int wid = tid >> 5;
    const int lid = tid & 31;
    const int wm = wid & 3;
    const int wn = wid >> 2;
    const int bm = blockIdx.y * 128;
    const int bn = blockIdx.x * 128;

    float acc[2][8][4];
    #pragma unroll
    for (int t = 0; t < 2; ++t)
        #pragma unroll
        for (int j = 0; j < 8; ++j)
            #pragma unroll
            for (int e = 0; e < 4; ++e) acc[t][j][e] = 0.f;

    const int a_row = (lid & 15);
    const int a_kb  = (lid & 16) ? 16 : 0;
    const int bsel  = lid >> 3;
    const int b_kin = (bsel & 1) * 8 + (lid & 7);
    const int b_nin = (bsel >> 1) * 8;

    auto load_stage = [&](char* sbase, int k0) {
        #pragma unroll
        for (int j = 0; j < 4; ++j) {
            int c = tid + j * 256;
            if (c < 512) {
                int r = c >> 2, ch = c & 3;
                const __half* src = A + (size_t)(bm + r) * KDIM + k0 + ch * 8;
                uint32_t dst = smem_u32(sbase);
                CP_ASYNC16(dst + SWZ64(r * 64 + ch * 16), src);
            } else {
                int cc = c - 512;
                int r = cc >> 4, ch = cc & 15;
                const __half* src = B + (size_t)(k0 + r) * Cw + bn + ch * 8;
                uint32_t dst = smem_u32(sbase + ST_TILEB);
                CP_ASYNC16(dst + SWZ256(r * 256 + ch * 16), src);
            }
        }
        CP_ASYNC_COMMIT();
    };

    load_stage(smem,            0);
    load_stage(smem + ST_STG_B, 32);

    int cur = 0;
    for (int i = 0; i < ST_NITER; ++i) {
        if (i + 1 < ST_NITER) { CP_ASYNC_WAIT(1); } else { CP_ASYNC_WAIT(0); }
        __syncthreads();

        char* sbase = smem + cur * ST_STG_B;
        const uint32_t tA = smem_u32(sbase);
        const uint32_t tB = tA + ST_TILEB;

        #pragma unroll
        for (int kk = 0; kk < 2; ++kk) {
            uint32_t av[2][4], bv[4][4];
            #pragma unroll
            for (int t = 0; t < 2; ++t) {
                int row = wm * 32 + t * 16 + a_row;
                LDSM_X4(av[t][0], av[t][1], av[t][2], av[t][3],
                        tA + SWZ64(row * 64 + kk * 32 + a_kb));
            }
            #pragma unroll
            for (int g = 0; g < 4; ++g) {
                int krow = kk * 16 + b_kin;
                int ncol = wn * 64 + g * 16 + b_nin;
                LDSM_X4_T(bv[g][0], bv[g][1], bv[g][2], bv[g][3],
                          tB + SWZ256(krow * 256 + ncol * 2));
            }
            #pragma unroll
            for (int t = 0; t < 2; ++t)
                #pragma unroll
                for (int g = 0; g < 4; ++g) {
                    MMA16816(acc[t][2 * g],     av[t], bv[g][0], bv[g][1]);
                    MMA16816(acc[t][2 * g + 1], av[t], bv[g][2], bv[g][3]);
                }
        }

        if (i + 2 < ST_NITER) {
            int nxt = cur + 2; if (nxt >= 3) nxt -= 3;
            load_stage(smem + nxt * ST_STG_B, (i + 2) * 32);
        }
        if (++cur == 3) cur = 0;
    }

    const int r0 = bm + wm * 32 + (lid >> 2);
    const int cb = bn + wn * 64 + (lid & 3) * 2;
    #pragma unroll
    for (int t = 0; t < 2; ++t)
        #pragma unroll
        for (int j = 0; j < 8; ++j) {
            float2 v0 = make_float2(acc[t][j][0], acc[t][j][1]);
            float2 v1 = make_float2(acc[t][j][2], acc[t][j][3]);
            *(float2*)(C + (size_t)(r0 + t * 16)     * Cw + cb + j * 8) = v0;
            *(float2*)(C + (size_t)(r0 + t * 16 + 8) * Cw + cb + j * 8) = v1;
        }
}

// ---------------- fused gate + mask + causal conv + Cg gate -----------------
#define CONV_CHUNK 64

__global__ __launch_bounds__(256)
void conv_kernel(const int* __restrict__ mask, const float* __restrict__ conv_w)
{
    const int h2 = (blockIdx.x * 256 + threadIdx.x) * 2;
    const int b  = blockIdx.z;
    const int t0 = blockIdx.y * CONV_CHUNK;

    const float* __restrict__ BC = g_BCx;
    __half*      __restrict__ Y  = g_yh;
    const int*   __restrict__ M  = mask + b * TT;

    float2 cw[LL];
    #pragma unroll
    for (int k = 0; k < LL; ++k) {
        cw[k].x = conv_w[h2 * LL + k];
        cw[k].y = conv_w[(h2 + 1) * LL + k];
    }

    float2 p1 = {0.f, 0.f}, p2 = {0.f, 0.f}, p3 = {0.f, 0.f};
    #pragma unroll
    for (int d = 3; d >= 1; --d) {
        int t = t0 - d;
        float2 bx = {0.f, 0.f};
        if (t >= 0 && M[t] != 0) {
            size_t base = ((size_t)(b * TT + t)) * N3H;
            float2 Bg = *(const float2*)(BC + base + h2);
            float2 xg = *(const float2*)(BC + base + 2 * HH + h2);
            bx.x = Bg.x * xg.x; bx.y = Bg.y * xg.y;
        }
        p3 = p2; p2 = p1; p1 = bx;
    }

    #pragma unroll 2
    for (int t = t0; t < t0 + CONV_CHUNK; ++t) {
        size_t base = ((size_t)(b * TT + t)) * N3H;
        float2 Bg = *(const float2*)(BC + base + h2);
        float2 Cg = *(const float2*)(BC + base + HH + h2);
        float2 xg = *(const float2*)(BC + base + 2 * HH + h2);
        bool m = (M[t] != 0);
        float2 bx;
        bx.x = m ? (Bg.x * xg.x) : 0.f;
        bx.y = m ? (Bg.y * xg.y) : 0.f;
        float2 conv;
        conv.x = cw[0].x * p3.x + cw[1].x * p2.x + cw[2].x * p1.x + cw[3].x * bx.x;
        conv.y = cw[0].y * p3.y + cw[1].y * p2.y + cw[2].y * p1.y + cw[3].y * bx.y;
        *(__half2*)(Y + ((size_t)(b * TT + t)) * HH + h2) =
            __floats2half2_rn(Cg.x * conv.x, Cg.y * conv.y);
        p3 = p2; p2 = p1; p1 = bx;
    }
}

// ---------------- launch -----------------------------------------------------
extern "C" void kernel_launch(void* const* d_in, const int* in_sizes, int n_in,
                              void* d_out, int out_size)
{
    const float* x      = (const float*)d_in[0];
    const int*   mask   = (const int*)d_in[1];    // bool widened to int32
    const float* W_in   = (const float*)d_in[2];
    const float* conv_w = (const float*)d_in[3];
    const float* W_out  = (const float*)d_in[4];
    float*       out    = (float*)d_out;

    // Try to enable the 96 KB dynamic-smem BK=64 variant; fall back if refused.
    static int use_dyn = -1;
    if (use_dyn < 0) {
        cudaError_t e = cudaFuncSetAttribute(
            gemm_mma_dyn, cudaFuncAttributeMaxDynamicSharedMemorySize, DYN_SMEM);
        use_dyn = (e == cudaSuccess) ? 1 : 0;
        if (!use_dyn) (void)cudaGetLastError();   // clear sticky error
    }

    // prep: elementwise fp32 -> fp16
    convert_x_kernel<<<(size_t)MROWS * HH / (256 * 4), 256>>>(x);
    convert_w_kernel<<<(size_t)HH * N3H / (256 * 4), 256>>>(W_in, 0);
    convert_w_kernel<<<(size_t)HH * HH / (256 * 4), 256>>>(W_out, 1);

    // GEMM1: BCx = x @ W_in
    if (use_dyn)
        gemm_mma_dyn<<<dim3(N3H / 128, MROWS / 128), 256, DYN_SMEM>>>(0, nullptr);
    else
        gemm_mma_static<<<dim3(N3H / 128, MROWS / 128), 256>>>(0, nullptr);

    // gate + conv + gate -> y (fp16)
    conv_kernel<<<dim3(HH / 512, TT / CONV_CHUNK, BB), 256>>>(mask, conv_w);

    // GEMM2: out = y @ W_out
    if (use_dyn)
        gemm_mma_dyn<<<dim3(HH / 128, MROWS / 128), 256, DYN_SMEM>>>(1, out);
    else
        gemm_mma_static<<<dim3(HH / 128, MROWS / 128), 256>>>(1, out);
}